// round 11
// baseline (speedup 1.0000x reference)
#include <cuda_runtime.h>
#include <cuda_bf16.h>
#include <cstdint>

typedef __nv_bfloat16 bf16;

// ---------------------------------------------------------------------------
// CrossModalAttention, sm_100:
//   stage 1    : bf16 GEMM (transposed epilogue)          -> thetaT
//   stages 2+3 : ONE bf16 GEMM, M=512 stacked weights,    -> phiT + gv
//   stages 4-7 : fused flash kernel; S_{j+1} mma overlapped with softmax_j
//                (3-deep kv buffering); out_w projection fused in epilogue.
// ---------------------------------------------------------------------------

__device__ bf16  g_w16   [4][65536];                 // thw, phw, gw, ow in bf16
__device__ bf16  g_CTb   [(size_t)8 * 4096 * 256];   // [B][Nq][CQ]
__device__ bf16  g_PTb   [(size_t)8 * 1024 * 256];   // [B][Nkv][CKV]
__device__ bf16  g_thetaT[(size_t)8 * 4096 * 256];   // [B][Nq][E] (pre-scaled 1/16)
__device__ bf16  g_phiT  [(size_t)8 * 1024 * 256];   // [B][Nkv][E]
__device__ bf16  g_gv    [(size_t)8 * 256 * 1024];   // [B][E][Nkv]

#define SWZ(x) ((x) ^ (((x) >> 3) & 0x70))

__device__ __forceinline__ uint32_t smem_u32(const void* p) {
    uint32_t a;
    asm("{ .reg .u64 t; cvta.to.shared.u64 t, %1; cvt.u32.u64 %0, t; }" : "=r"(a) : "l"(p));
    return a;
}
__device__ __forceinline__ void cp16(uint32_t dst, const void* src) {
    asm volatile("cp.async.cg.shared.global [%0], [%1], 16;" :: "r"(dst), "l"(src) : "memory");
}
__device__ __forceinline__ void ldsm4(uint32_t* r, uint32_t a) {
    asm volatile("ldmatrix.sync.aligned.m8n8.x4.shared.b16 {%0,%1,%2,%3}, [%4];"
        : "=r"(r[0]), "=r"(r[1]), "=r"(r[2]), "=r"(r[3]) : "r"(a));
}
__device__ __forceinline__ void mma_bf16(float* c, const uint32_t* a, uint32_t b0, uint32_t b1) {
    asm volatile(
        "mma.sync.aligned.m16n8k16.row.col.f32.bf16.bf16.f32 "
        "{%0,%1,%2,%3},{%4,%5,%6,%7},{%8,%9},{%0,%1,%2,%3};"
        : "+f"(c[0]), "+f"(c[1]), "+f"(c[2]), "+f"(c[3])
        : "r"(a[0]), "r"(a[1]), "r"(a[2]), "r"(a[3]), "r"(b0), "r"(b1));
}
__device__ __forceinline__ void bar_pair(int id) {
    asm volatile("bar.sync %0, 64;" :: "r"(id) : "memory");
}

// ================= generic bf16 GEMM (stages 1, 2+3 merged) =================
__global__ __launch_bounds__(256) void gemm_bf16_kernel(
    const bf16* __restrict__ A, const bf16* __restrict__ B,
    bf16* __restrict__ Out, bf16* __restrict__ Out2,
    int K, int as, long aB, int bs, long bB,
    long oB, int ldO, long oB2, int ldO2, float alpha)
{
    extern __shared__ char smem[];
    const uint32_t sb = smem_u32(smem);
    const int tid = threadIdx.x, warp = tid >> 5, lane = tid & 31;
    const int m0 = blockIdx.x * 128, n0 = blockIdx.y * 128;
    const bf16* Ab = A + (long)blockIdx.z * aB + (long)m0 * as;
    const bf16* Bb = B + (long)blockIdx.z * bB + (long)n0 * bs;

    int crow[4], ckc[4]; uint32_t cdst[4];
    #pragma unroll
    for (int j = 0; j < 4; j++) {
        int idx = tid + j * 256;
        crow[j] = idx >> 3; ckc[j] = idx & 7;
        cdst[j] = SWZ((uint32_t)(crow[j] * 128 + ckc[j] * 16));
    }
    const int nk = K >> 6;

    #define ISSUE(IT) do {                                                    \
        int _kt = (IT) * 64;                                                  \
        uint32_t _sA = sb + ((IT) % 3) * 32768, _sB = _sA + 16384;            \
        _Pragma("unroll")                                                     \
        for (int j = 0; j < 4; j++) {                                         \
            cp16(_sA + cdst[j], Ab + (long)crow[j] * as + _kt + ckc[j] * 8);  \
            cp16(_sB + cdst[j], Bb + (long)crow[j] * bs + _kt + ckc[j] * 8);  \
        }                                                                     \
    } while (0)

    #pragma unroll
    for (int s = 0; s < 2; s++) {
        if (s < nk) ISSUE(s);
        asm volatile("cp.async.commit_group;" ::: "memory");
    }

    float acc[4][4][4];
    #pragma unroll
    for (int i = 0; i < 4; i++)
        #pragma unroll
        for (int j = 0; j < 4; j++)
            #pragma unroll
            for (int r = 0; r < 4; r++) acc[i][j][r] = 0.0f;

    const int wm = warp & 1, wn = warp >> 1;
    const int arow = lane & 15;
    const int ksel = (lane >> 4) * 16;

    for (int it = 0; it < nk; it++) {
        if (it + 2 < nk) ISSUE(it + 2);
        asm volatile("cp.async.commit_group;" ::: "memory");
        asm volatile("cp.async.wait_group 2;" ::: "memory");
        __syncthreads();

        const uint32_t sA = sb + (it % 3) * 32768, sB = sA + 16384;
        #pragma unroll
        for (int ks = 0; ks < 64; ks += 16) {
            uint32_t af[4][4], bfr[2][4];
            #pragma unroll
            for (int mt = 0; mt < 4; mt++)
                ldsm4(af[mt], sA + SWZ((uint32_t)((wm * 64 + mt * 16 + arow) * 128 + ks * 2 + ksel)));
            #pragma unroll
            for (int h = 0; h < 2; h++)
                ldsm4(bfr[h], sB + SWZ((uint32_t)((wn * 32 + h * 16 + arow) * 128 + ks * 2 + ksel)));
            #pragma unroll
            for (int mt = 0; mt < 4; mt++)
                #pragma unroll
                for (int nt = 0; nt < 4; nt++)
                    mma_bf16(acc[mt][nt], af[mt],
                             bfr[nt >> 1][nt & 1], bfr[nt >> 1][(nt & 1) + 2]);
        }
        __syncthreads();
    }

    const int gid = lane >> 2, tg = lane & 3;
    const bool second = (Out2 != nullptr) && (m0 >= 256);
    #pragma unroll
    for (int mt = 0; mt < 4; mt++) {
        const int row = m0 + wm * 64 + mt * 16 + gid;
        #pragma unroll
        for (int nt = 0; nt < 4; nt++) {
            const int col = n0 + wn * 32 + nt * 8 + tg * 2;
            float v0 = acc[mt][nt][0] * alpha, v1 = acc[mt][nt][1] * alpha;
            float v2 = acc[mt][nt][2] * alpha, v3 = acc[mt][nt][3] * alpha;
            if (second) {
                bf16* O = Out2 + (long)blockIdx.z * oB2;
                const int r2 = row - 256;
                *(__nv_bfloat162*)&O[(long)r2 * ldO2 + col]       = __floats2bfloat162_rn(v0, v1);
                *(__nv_bfloat162*)&O[(long)(r2 + 8) * ldO2 + col] = __floats2bfloat162_rn(v2, v3);
            } else {
                bf16* O = Out + (long)blockIdx.z * oB;
                O[(long)col * ldO + row]           = __float2bfloat16(v0);
                O[(long)(col + 1) * ldO + row]     = __float2bfloat16(v1);
                O[(long)col * ldO + row + 8]       = __float2bfloat16(v2);
                O[(long)(col + 1) * ldO + row + 8] = __float2bfloat16(v3);
            }
        }
    }
}

// ================= fused flash kernel (stages 4,5,6,7) =================
// smem: [0,32K) theta staging -> reused as P tile -> reused as O tile;
//       kv buffers: 3 x 64K at 32K/96K/160K (phi 32K + gv 32K each);
//       stats at 224K. Total 225K + 1K.
#define FL_KV(i) (32768 + (i) * 65536)
#define FL_STATS (32768 + 3 * 65536)
#define FL_TOTAL (FL_STATS + 1024)

__global__ __launch_bounds__(256) void flash_kernel(
    const bf16* __restrict__ Th, const bf16* __restrict__ Ph,
    const bf16* __restrict__ Gv, const bf16* __restrict__ Ow,
    float* __restrict__ OutF)
{
    extern __shared__ char smem[];
    const uint32_t sb = smem_u32(smem);
    const int tid = threadIdx.x, warp = tid >> 5, lane = tid & 31;
    const int WM = warp >> 1, WN = warp & 1;
    const int gid = lane >> 2, tg = lane & 3;
    const int arow = lane & 15, ksel = (lane >> 4) * 16;
    const int q0 = blockIdx.x * 64, z = blockIdx.y;

    const bf16* ThB = Th + ((long)z * 4096 + q0) * 256;
    const bf16* PhB = Ph + (long)z * 1024 * 256;
    const bf16* GvB = Gv + (long)z * 256 * 1024;

    auto issue_kv = [&](int jj, uint32_t kvbase) {
        const bf16* ph = PhB + jj * 64 * 256;
        #pragma unroll
        for (int j = 0; j < 8; j++) {
            int i = tid + j * 256, row = i >> 5, c16 = i & 31;
            cp16(kvbase + (c16 >> 3) * 8192 + SWZ((uint32_t)(row * 128 + (c16 & 7) * 16)),
                 ph + row * 256 + c16 * 8);
        }
        const bf16* gvp = GvB + jj * 64;
        #pragma unroll
        for (int j = 0; j < 8; j++) {
            int i = tid + j * 256, e = i >> 3, cw = i & 7;
            cp16(kvbase + 32768 + SWZ((uint32_t)(e * 128 + cw * 16)),
                 gvp + e * 1024 + cw * 8);
        }
    };
    auto issue_ow = [&](int cs, uint32_t kvbase) {
        const bf16* owp = Ow + cs * 64 * 256;
        #pragma unroll
        for (int j = 0; j < 8; j++) {
            int i = tid + j * 256, row = i >> 5, c16 = i & 31;
            cp16(kvbase + (c16 >> 3) * 8192 + SWZ((uint32_t)(row * 128 + (c16 & 7) * 16)),
                 owp + row * 256 + c16 * 8);
        }
    };

    // prologue: G0 = theta + kv0, G1 = kv1, G2 = kv2
    #pragma unroll
    for (int j = 0; j < 8; j++) {
        int i = tid + j * 256, row = i >> 5, c16 = i & 31;
        cp16(sb + (c16 >> 3) * 8192 + SWZ((uint32_t)(row * 128 + (c16 & 7) * 16)),
             ThB + row * 256 + c16 * 8);
    }
    issue_kv(0, sb + FL_KV(0));
    asm volatile("cp.async.commit_group;" ::: "memory");
    issue_kv(1, sb + FL_KV(1));
    asm volatile("cp.async.commit_group;" ::: "memory");
    issue_kv(2, sb + FL_KV(2));
    asm volatile("cp.async.commit_group;" ::: "memory");

    asm volatile("cp.async.wait_group 2;" ::: "memory");
    __syncthreads();
    uint32_t af_all[4][4][4];
    #pragma unroll
    for (int slab = 0; slab < 4; slab++)
        #pragma unroll
        for (int ks = 0; ks < 4; ks++)
            ldsm4(af_all[slab][ks],
                  sb + slab * 8192 + SWZ((uint32_t)((WM * 16 + arow) * 128 + ks * 32 + ksel)));
    __syncthreads();   // staging now reusable as P

    float m_lo = -1e30f, m_hi = -1e30f, l_lo = 0.0f, l_hi = 0.0f;
    float acc_o[16][4];
    #pragma unroll
    for (int i = 0; i < 16; i++)
        #pragma unroll
        for (int r = 0; r < 4; r++) acc_o[i][r] = 0.0f;

    const int rlo = WM * 16 + gid, rhi = rlo + 8;
    float* pmax = (float*)(smem + FL_STATS);
    float* psum = (float*)(smem + FL_STATS + 512);
    const int barid = WM + 1;

    // S = theta . phi^T (64x64, K=256) from the given kv buffer
    auto compute_S = [&](uint32_t kvbase, float (*s)[4]) {
        #pragma unroll
        for (int i = 0; i < 4; i++)
            #pragma unroll
            for (int r = 0; r < 4; r++) s[i][r] = 0.0f;
        #pragma unroll
        for (int slab = 0; slab < 4; slab++) {
            const uint32_t phS = kvbase + slab * 8192;
            #pragma unroll
            for (int ks = 0; ks < 4; ks++) {
                uint32_t bfr[2][4];
                ldsm4(bfr[0], phS + SWZ((uint32_t)((WN * 32 + arow) * 128 + ks * 32 + ksel)));
                ldsm4(bfr[1], phS + SWZ((uint32_t)((WN * 32 + 16 + arow) * 128 + ks * 32 + ksel)));
                #pragma unroll
                for (int nt = 0; nt < 4; nt++)
                    mma_bf16(s[nt], af_all[slab][ks],
                             bfr[nt >> 1][nt & 1], bfr[nt >> 1][(nt & 1) + 2]);
            }
        }
    };

    float s_cur[4][4], s_next[4][4];
    compute_S(sb + FL_KV(0), s_cur);   // kv0 is ready (G0 waited)

    for (int it = 0; it < 16; it++) {
        // 1) issue next tile's S-mma first: tensor work that overlaps softmax
        if (it + 1 < 16) {
            asm volatile("cp.async.wait_group 1;" ::: "memory");   // kv_{it+1} done
            __syncthreads();
            compute_S(sb + FL_KV((it + 1) % 3), s_next);
        }

        // 2) online softmax on s_cur (ALU/MUFU; overlaps tensor above)
        float vlo = -1e30f, vhi = -1e30f;
        #pragma unroll
        for (int nt = 0; nt < 4; nt++) {
            vlo = fmaxf(vlo, fmaxf(s_cur[nt][0], s_cur[nt][1]));
            vhi = fmaxf(vhi, fmaxf(s_cur[nt][2], s_cur[nt][3]));
        }
        vlo = fmaxf(vlo, __shfl_xor_sync(0xffffffffu, vlo, 1));
        vlo = fmaxf(vlo, __shfl_xor_sync(0xffffffffu, vlo, 2));
        vhi = fmaxf(vhi, __shfl_xor_sync(0xffffffffu, vhi, 1));
        vhi = fmaxf(vhi, __shfl_xor_sync(0xffffffffu, vhi, 2));
        if (tg == 0) { pmax[WN * 64 + rlo] = vlo; pmax[WN * 64 + rhi] = vhi; }
        bar_pair(barid);
        const float mnlo = fmaxf(m_lo, fmaxf(pmax[rlo], pmax[64 + rlo]));
        const float mnhi = fmaxf(m_hi, fmaxf(pmax[rhi], pmax[64 + rhi]));
        const float clo = __expf(m_lo - mnlo), chi = __expf(m_hi - mnhi);
        m_lo = mnlo; m_hi = mnhi;

        float slo = 0.0f, shi = 0.0f;
        #pragma unroll
        for (int nt = 0; nt < 4; nt++) {
            s_cur[nt][0] = __expf(s_cur[nt][0] - mnlo);
            s_cur[nt][1] = __expf(s_cur[nt][1] - mnlo);
            s_cur[nt][2] = __expf(s_cur[nt][2] - mnhi);
            s_cur[nt][3] = __expf(s_cur[nt][3] - mnhi);
            slo += s_cur[nt][0] + s_cur[nt][1];
            shi += s_cur[nt][2] + s_cur[nt][3];
        }
        l_lo = l_lo * clo + slo;
        l_hi = l_hi * chi + shi;

        #pragma unroll
        for (int nt = 0; nt < 16; nt++) {
            acc_o[nt][0] *= clo; acc_o[nt][1] *= clo;
            acc_o[nt][2] *= chi; acc_o[nt][3] *= chi;
        }

        // 3) P tile into staging
        #pragma unroll
        for (int nt = 0; nt < 4; nt++) {
            const int col = WN * 32 + nt * 8 + tg * 2;
            *(__nv_bfloat162*)(smem + SWZ((uint32_t)(rlo * 128 + col * 2))) =
                __floats2bfloat162_rn(s_cur[nt][0], s_cur[nt][1]);
            *(__nv_bfloat162*)(smem + SWZ((uint32_t)(rhi * 128 + col * 2))) =
                __floats2bfloat162_rn(s_cur[nt][2], s_cur[nt][3]);
        }
        bar_pair(barid);

        // 4) O += P . gv^T (gv of the CURRENT tile's buffer)
        const uint32_t gvS = sb + FL_KV(it % 3) + 32768;
        #pragma unroll
        for (int ks = 0; ks < 4; ks++) {
            uint32_t pf[4];
            ldsm4(pf, sb + SWZ((uint32_t)((WM * 16 + arow) * 128 + ks * 32 + ksel)));
            #pragma unroll
            for (int h = 0; h < 8; h++) {
                uint32_t gf[4];
                ldsm4(gf, gvS + SWZ((uint32_t)((WN * 128 + h * 16 + arow) * 128 + ks * 32 + ksel)));
                mma_bf16(acc_o[2 * h],     pf, gf[0], gf[2]);
                mma_bf16(acc_o[2 * h + 1], pf, gf[1], gf[3]);
            }
        }
        __syncthreads();   // all reads of kv_it and P done

        // 5) refill the buffer just drained with kv_{it+3}
        if (it + 3 < 16) {
            issue_kv(it + 3, sb + FL_KV(it % 3));
            asm volatile("cp.async.commit_group;" ::: "memory");
        }

        // 6) rotate S registers
        if (it + 1 < 16) {
            #pragma unroll
            for (int i = 0; i < 4; i++)
                #pragma unroll
                for (int r = 0; r < 4; r++) s_cur[i][r] = s_next[i][r];
        }
    }

    // stream ow through kv buffers 0/1 (all kv reads complete)
    issue_ow(0, sb + FL_KV(0));
    asm volatile("cp.async.commit_group;" ::: "memory");
    issue_ow(1, sb + FL_KV(1));
    asm volatile("cp.async.commit_group;" ::: "memory");

    // final l reduction
    l_lo += __shfl_xor_sync(0xffffffffu, l_lo, 1);
    l_lo += __shfl_xor_sync(0xffffffffu, l_lo, 2);
    l_hi += __shfl_xor_sync(0xffffffffu, l_hi, 1);
    l_hi += __shfl_xor_sync(0xffffffffu, l_hi, 2);
    if (tg == 0) { psum[WN * 64 + rlo] = l_lo; psum[WN * 64 + rhi] = l_hi; }
    bar_pair(barid);
    const float ilo = 1.0f / (psum[rlo] + psum[64 + rlo]);
    const float ihi = 1.0f / (psum[rhi] + psum[64 + rhi]);

    // normalized O (bf16) into staging as 4 e-slabs of [64q x 128B]
    #pragma unroll
    for (int nt = 0; nt < 16; nt++) {
        const int e = WN * 128 + nt * 8 + tg * 2;
        const int slab = e >> 6, el = e & 63;
        *(__nv_bfloat162*)(smem + slab * 8192 + SWZ((uint32_t)(rlo * 128 + el * 2))) =
            __floats2bfloat162_rn(acc_o[nt][0] * ilo, acc_o[nt][1] * ilo);
        *(__nv_bfloat162*)(smem + slab * 8192 + SWZ((uint32_t)(rhi * 128 + el * 2))) =
            __floats2bfloat162_rn(acc_o[nt][2] * ihi, acc_o[nt][3] * ihi);
    }
    __syncthreads();

    // O fragments (A operand of the projection GEMM)
    uint32_t of[4][4][4];
    #pragma unroll
    for (int slab = 0; slab < 4; slab++)
        #pragma unroll
        for (int ks = 0; ks < 4; ks++)
            ldsm4(of[slab][ks],
                  sb + slab * 8192 + SWZ((uint32_t)((WM * 16 + arow) * 128 + ks * 32 + ksel)));

    // F[q][c] = O . ow^T, 4 c-slabs of 64, written f32 to out
    float* out2 = OutF + (long)z * (512L * 4096) + 256L * 4096 + q0;
    for (int cs = 0; cs < 4; cs++) {
        const uint32_t kvc = sb + FL_KV(cs & 1);
        if (cs < 3) { asm volatile("cp.async.wait_group 1;" ::: "memory"); }
        else        { asm volatile("cp.async.wait_group 0;" ::: "memory"); }
        __syncthreads();

        float accf[4][4];
        #pragma unroll
        for (int i = 0; i < 4; i++)
            #pragma unroll
            for (int r = 0; r < 4; r++) accf[i][r] = 0.0f;

        #pragma unroll
        for (int slab = 0; slab < 4; slab++) {
            const uint32_t wS = kvc + slab * 8192;
            #pragma unroll
            for (int ks = 0; ks < 4; ks++) {
                uint32_t bfr[2][4];
                ldsm4(bfr[0], wS + SWZ((uint32_t)((WN * 32 + arow) * 128 + ks * 32 + ksel)));
                ldsm4(bfr[1], wS + SWZ((uint32_t)((WN * 32 + 16 + arow) * 128 + ks * 32 + ksel)));
                #pragma unroll
                for (int nt = 0; nt < 4; nt++)
                    mma_bf16(accf[nt], of[slab][ks],
                             bfr[nt >> 1][nt & 1], bfr[nt >> 1][(nt & 1) + 2]);
            }
        }

        #pragma unroll
        for (int nt = 0; nt < 4; nt++) {
            const int c = cs * 64 + WN * 32 + nt * 8 + tg * 2;
            out2[(long)c * 4096 + rlo]       = accf[nt][0];
            out2[(long)(c + 1) * 4096 + rlo] = accf[nt][1];
            out2[(long)c * 4096 + rhi]       = accf[nt][2];
            out2[(long)(c + 1) * 4096 + rhi] = accf[nt][3];
        }

        if (cs + 2 < 4) {
            __syncthreads();
            issue_ow(cs + 2, kvc);
            asm volatile("cp.async.commit_group;" ::: "memory");
        }
    }
}

// ============== transpose+convert (+ optional copy-through to out) ==============
__global__ __launch_bounds__(256) void transcvt_kernel(
    const float* __restrict__ in, bf16* __restrict__ out,
    float* __restrict__ copyDst, int Cc)
{
    __shared__ float t[32][33];
    const long base = (long)blockIdx.z * 256 * Cc;
    const int c0 = blockIdx.x * 32, r0 = blockIdx.y * 32;
    const int tx = threadIdx.x, ty = threadIdx.y;
    #pragma unroll
    for (int i = 0; i < 4; i++) {
        float v = in[base + (long)(r0 + ty + i * 8) * Cc + c0 + tx];
        t[ty + i * 8][tx] = v;
        if (copyDst)
            copyDst[(long)blockIdx.z * (512L * 4096) + (long)(r0 + ty + i * 8) * Cc + c0 + tx] = v;
    }
    __syncthreads();
    #pragma unroll
    for (int i = 0; i < 4; i++)
        out[base + (long)(c0 + ty + i * 8) * 256 + r0 + tx] = __float2bfloat16(t[tx][ty + i * 8]);
}

__global__ __launch_bounds__(256) void cvt4_kernel(
    const float* __restrict__ a, const float* __restrict__ b,
    const float* __restrict__ c, const float* __restrict__ d,
    bf16* __restrict__ out)
{
    const float* srcs[4] = {a, b, c, d};
    int j = (blockIdx.x * 256 + threadIdx.x) * 4;
    float4 v = *(const float4*)(srcs[j >> 16] + (j & 65535));
    *(__nv_bfloat162*)&out[j]     = __floats2bfloat162_rn(v.x, v.y);
    *(__nv_bfloat162*)&out[j + 2] = __floats2bfloat162_rn(v.z, v.w);
}

extern "C" void kernel_launch(void* const* d_in, const int* in_sizes, int n_in,
                              void* d_out, int out_size)
{
    const float* C   = (const float*)d_in[0];
    const float* P   = (const float*)d_in[1];
    const float* thw = (const float*)d_in[2];
    const float* phw = (const float*)d_in[3];
    const float* gw  = (const float*)d_in[4];
    const float* ow  = (const float*)d_in[5];
    float* out = (float*)d_out;

    bf16 *w16, *CTb, *PTb, *thetaT, *phiT, *gv;
    cudaGetSymbolAddress((void**)&w16, g_w16);
    cudaGetSymbolAddress((void**)&CTb, g_CTb);
    cudaGetSymbolAddress((void**)&PTb, g_PTb);
    cudaGetSymbolAddress((void**)&thetaT, g_thetaT);
    cudaGetSymbolAddress((void**)&phiT, g_phiT);
    cudaGetSymbolAddress((void**)&gv, g_gv);

    static int attr_set = 0;
    if (!attr_set) {
        cudaFuncSetAttribute(gemm_bf16_kernel,
                             cudaFuncAttributeMaxDynamicSharedMemorySize, 98304);
        cudaFuncSetAttribute(flash_kernel,
                             cudaFuncAttributeMaxDynamicSharedMemorySize, FL_TOTAL);
        attr_set = 1;
    }

    const dim3 blk(256);
    const long NQ = 4096, NKV = 1024;

    cvt4_kernel<<<256, blk>>>(thw, phw, gw, ow, w16);
    transcvt_kernel<<<dim3(128, 8, 8), dim3(32, 8)>>>(C, CTb, out, 4096);
    transcvt_kernel<<<dim3(32, 8, 8), dim3(32, 8)>>>(P, PTb, nullptr, 1024);

    // 1) thetaT[nq][e] = (thw @ C) / 16   (transposed bf16)
    gemm_bf16_kernel<<<dim3(2, 32, 8), blk, 98304>>>(w16, CTb, thetaT, nullptr, 256,
        256, 0, 256, NQ * 256, NQ * 256, 256, 0, 0, 0.0625f);
    // 2+3) stacked [phw;gw] @ P: m0<256 -> phiT (trans), m0>=256 -> gv (normal)
    gemm_bf16_kernel<<<dim3(4, 8, 8), blk, 98304>>>(w16 + 65536, PTb, phiT, gv, 256,
        256, 0, 256, NKV * 256, NKV * 256, 256, 256 * NKV, 1024, 1.0f);
    // 4-7) fused attention + output projection (writes out second half, f32)
    flash_kernel<<<dim3(64, 8), blk, FL_TOTAL>>>(thetaT, phiT, gv, w16 + 3 * 65536, out);
}

// round 13
// speedup vs baseline: 1.0419x; 1.0419x over previous
#include <cuda_runtime.h>
#include <cuda_bf16.h>
#include <cstdint>

typedef __nv_bfloat16 bf16;

// ---------------------------------------------------------------------------
// CrossModalAttention, sm_100:
//   stream-parallel prologue:
//     s0: cvt4 -> transcvtC -> stage1(thetaT)
//     s1: transcvtP -> stage2+3(phiT,gv)       (event fork/join)
//   then: fused flash kernel (stages 4-7) incl. out_w projection.
// ---------------------------------------------------------------------------

__device__ bf16  g_w16   [4][65536];                 // thw, phw, gw, ow in bf16
__device__ bf16  g_CTb   [(size_t)8 * 4096 * 256];   // [B][Nq][CQ]
__device__ bf16  g_PTb   [(size_t)8 * 1024 * 256];   // [B][Nkv][CKV]
__device__ bf16  g_thetaT[(size_t)8 * 4096 * 256];   // [B][Nq][E] (pre-scaled 1/16)
__device__ bf16  g_phiT  [(size_t)8 * 1024 * 256];   // [B][Nkv][E]
__device__ bf16  g_gv    [(size_t)8 * 256 * 1024];   // [B][E][Nkv]

#define SWZ(x) ((x) ^ (((x) >> 3) & 0x70))

__device__ __forceinline__ uint32_t smem_u32(const void* p) {
    uint32_t a;
    asm("{ .reg .u64 t; cvta.to.shared.u64 t, %1; cvt.u32.u64 %0, t; }" : "=r"(a) : "l"(p));
    return a;
}
__device__ __forceinline__ void cp16(uint32_t dst, const void* src) {
    asm volatile("cp.async.cg.shared.global [%0], [%1], 16;" :: "r"(dst), "l"(src) : "memory");
}
__device__ __forceinline__ void ldsm4(uint32_t* r, uint32_t a) {
    asm volatile("ldmatrix.sync.aligned.m8n8.x4.shared.b16 {%0,%1,%2,%3}, [%4];"
        : "=r"(r[0]), "=r"(r[1]), "=r"(r[2]), "=r"(r[3]) : "r"(a));
}
__device__ __forceinline__ void mma_bf16(float* c, const uint32_t* a, uint32_t b0, uint32_t b1) {
    asm volatile(
        "mma.sync.aligned.m16n8k16.row.col.f32.bf16.bf16.f32 "
        "{%0,%1,%2,%3},{%4,%5,%6,%7},{%8,%9},{%0,%1,%2,%3};"
        : "+f"(c[0]), "+f"(c[1]), "+f"(c[2]), "+f"(c[3])
        : "r"(a[0]), "r"(a[1]), "r"(a[2]), "r"(a[3]), "r"(b0), "r"(b1));
}
__device__ __forceinline__ void bar_pair(int id) {
    asm volatile("bar.sync %0, 64;" :: "r"(id) : "memory");
}

// ================= generic bf16 GEMM (stages 1, 2+3 merged) =================
__global__ __launch_bounds__(256) void gemm_bf16_kernel(
    const bf16* __restrict__ A, const bf16* __restrict__ B,
    bf16* __restrict__ Out, bf16* __restrict__ Out2,
    int K, int as, long aB, int bs, long bB,
    long oB, int ldO, long oB2, int ldO2, float alpha)
{
    extern __shared__ char smem[];
    const uint32_t sb = smem_u32(smem);
    const int tid = threadIdx.x, warp = tid >> 5, lane = tid & 31;
    const int m0 = blockIdx.x * 128, n0 = blockIdx.y * 128;
    const bf16* Ab = A + (long)blockIdx.z * aB + (long)m0 * as;
    const bf16* Bb = B + (long)blockIdx.z * bB + (long)n0 * bs;

    int crow[4], ckc[4]; uint32_t cdst[4];
    #pragma unroll
    for (int j = 0; j < 4; j++) {
        int idx = tid + j * 256;
        crow[j] = idx >> 3; ckc[j] = idx & 7;
        cdst[j] = SWZ((uint32_t)(crow[j] * 128 + ckc[j] * 16));
    }
    const int nk = K >> 6;

    #define ISSUE(IT) do {                                                    \
        int _kt = (IT) * 64;                                                  \
        uint32_t _sA = sb + ((IT) % 3) * 32768, _sB = _sA + 16384;            \
        _Pragma("unroll")                                                     \
        for (int j = 0; j < 4; j++) {                                         \
            cp16(_sA + cdst[j], Ab + (long)crow[j] * as + _kt + ckc[j] * 8);  \
            cp16(_sB + cdst[j], Bb + (long)crow[j] * bs + _kt + ckc[j] * 8);  \
        }                                                                     \
    } while (0)

    #pragma unroll
    for (int s = 0; s < 2; s++) {
        if (s < nk) ISSUE(s);
        asm volatile("cp.async.commit_group;" ::: "memory");
    }

    float acc[4][4][4];
    #pragma unroll
    for (int i = 0; i < 4; i++)
        #pragma unroll
        for (int j = 0; j < 4; j++)
            #pragma unroll
            for (int r = 0; r < 4; r++) acc[i][j][r] = 0.0f;

    const int wm = warp & 1, wn = warp >> 1;
    const int arow = lane & 15;
    const int ksel = (lane >> 4) * 16;

    for (int it = 0; it < nk; it++) {
        if (it + 2 < nk) ISSUE(it + 2);
        asm volatile("cp.async.commit_group;" ::: "memory");
        asm volatile("cp.async.wait_group 2;" ::: "memory");
        __syncthreads();

        const uint32_t sA = sb + (it % 3) * 32768, sB = sA + 16384;
        #pragma unroll
        for (int ks = 0; ks < 64; ks += 16) {
            uint32_t af[4][4], bfr[2][4];
            #pragma unroll
            for (int mt = 0; mt < 4; mt++)
                ldsm4(af[mt], sA + SWZ((uint32_t)((wm * 64 + mt * 16 + arow) * 128 + ks * 2 + ksel)));
            #pragma unroll
            for (int h = 0; h < 2; h++)
                ldsm4(bfr[h], sB + SWZ((uint32_t)((wn * 32 + h * 16 + arow) * 128 + ks * 2 + ksel)));
            #pragma unroll
            for (int mt = 0; mt < 4; mt++)
                #pragma unroll
                for (int nt = 0; nt < 4; nt++)
                    mma_bf16(acc[mt][nt], af[mt],
                             bfr[nt >> 1][nt & 1], bfr[nt >> 1][(nt & 1) + 2]);
        }
        __syncthreads();
    }

    const int gid = lane >> 2, tg = lane & 3;
    const bool second = (Out2 != nullptr) && (m0 >= 256);
    #pragma unroll
    for (int mt = 0; mt < 4; mt++) {
        const int row = m0 + wm * 64 + mt * 16 + gid;
        #pragma unroll
        for (int nt = 0; nt < 4; nt++) {
            const int col = n0 + wn * 32 + nt * 8 + tg * 2;
            float v0 = acc[mt][nt][0] * alpha, v1 = acc[mt][nt][1] * alpha;
            float v2 = acc[mt][nt][2] * alpha, v3 = acc[mt][nt][3] * alpha;
            if (second) {
                bf16* O = Out2 + (long)blockIdx.z * oB2;
                const int r2 = row - 256;
                *(__nv_bfloat162*)&O[(long)r2 * ldO2 + col]       = __floats2bfloat162_rn(v0, v1);
                *(__nv_bfloat162*)&O[(long)(r2 + 8) * ldO2 + col] = __floats2bfloat162_rn(v2, v3);
            } else {
                bf16* O = Out + (long)blockIdx.z * oB;
                O[(long)col * ldO + row]           = __float2bfloat16(v0);
                O[(long)(col + 1) * ldO + row]     = __float2bfloat16(v1);
                O[(long)col * ldO + row + 8]       = __float2bfloat16(v2);
                O[(long)(col + 1) * ldO + row + 8] = __float2bfloat16(v3);
            }
        }
    }
}

// ================= fused flash kernel (stages 4,5,6,7) =================
// smem: [0,32K) theta staging -> reused as P tile -> reused as O tile;
//       kv0 32K..96K ; kv1 96K..160K (mainloop: phi+gv; epilogue: ow slabs);
//       stats at 160K.
#define FL_KV0   32768
#define FL_KV1   98304
#define FL_STATS 163840
#define FL_TOTAL 164864

__global__ __launch_bounds__(256) void flash_kernel(
    const bf16* __restrict__ Th, const bf16* __restrict__ Ph,
    const bf16* __restrict__ Gv, const bf16* __restrict__ Ow,
    float* __restrict__ OutF)
{
    extern __shared__ char smem[];
    const uint32_t sb = smem_u32(smem);
    const int tid = threadIdx.x, warp = tid >> 5, lane = tid & 31;
    const int WM = warp >> 1, WN = warp & 1;
    const int gid = lane >> 2, tg = lane & 3;
    const int arow = lane & 15, ksel = (lane >> 4) * 16;
    const int q0 = blockIdx.x * 64, z = blockIdx.y;

    const bf16* ThB = Th + ((long)z * 4096 + q0) * 256;
    const bf16* PhB = Ph + (long)z * 1024 * 256;
    const bf16* GvB = Gv + (long)z * 256 * 1024;

    auto issue_kv = [&](int jj, uint32_t kvbase) {
        const bf16* ph = PhB + jj * 64 * 256;
        #pragma unroll
        for (int j = 0; j < 8; j++) {
            int i = tid + j * 256, row = i >> 5, c16 = i & 31;
            cp16(kvbase + (c16 >> 3) * 8192 + SWZ((uint32_t)(row * 128 + (c16 & 7) * 16)),
                 ph + row * 256 + c16 * 8);
        }
        const bf16* gvp = GvB + jj * 64;
        #pragma unroll
        for (int j = 0; j < 8; j++) {
            int i = tid + j * 256, e = i >> 3, cw = i & 7;
            cp16(kvbase + 32768 + SWZ((uint32_t)(e * 128 + cw * 16)),
                 gvp + e * 1024 + cw * 8);
        }
    };
    auto issue_ow = [&](int cs, uint32_t kvbase) {
        const bf16* owp = Ow + cs * 64 * 256;
        #pragma unroll
        for (int j = 0; j < 8; j++) {
            int i = tid + j * 256, row = i >> 5, c16 = i & 31;
            cp16(kvbase + (c16 >> 3) * 8192 + SWZ((uint32_t)(row * 128 + (c16 & 7) * 16)),
                 owp + row * 256 + c16 * 8);
        }
    };

    // prologue: theta (group 0 with kv0), kv1 (group 1)
    #pragma unroll
    for (int j = 0; j < 8; j++) {
        int i = tid + j * 256, row = i >> 5, c16 = i & 31;
        cp16(sb + (c16 >> 3) * 8192 + SWZ((uint32_t)(row * 128 + (c16 & 7) * 16)),
             ThB + row * 256 + c16 * 8);
    }
    issue_kv(0, sb + FL_KV0);
    asm volatile("cp.async.commit_group;" ::: "memory");
    issue_kv(1, sb + FL_KV1);
    asm volatile("cp.async.commit_group;" ::: "memory");

    asm volatile("cp.async.wait_group 1;" ::: "memory");
    __syncthreads();
    uint32_t af_all[4][4][4];
    #pragma unroll
    for (int slab = 0; slab < 4; slab++)
        #pragma unroll
        for (int ks = 0; ks < 4; ks++)
            ldsm4(af_all[slab][ks],
                  sb + slab * 8192 + SWZ((uint32_t)((WM * 16 + arow) * 128 + ks * 32 + ksel)));
    __syncthreads();   // staging now reusable as P

    float m_lo = -1e30f, m_hi = -1e30f, l_lo = 0.0f, l_hi = 0.0f;
    float acc_o[16][4];
    #pragma unroll
    for (int i = 0; i < 16; i++)
        #pragma unroll
        for (int r = 0; r < 4; r++) acc_o[i][r] = 0.0f;

    const int rlo = WM * 16 + gid, rhi = rlo + 8;
    float* pmax = (float*)(smem + FL_STATS);
    float* psum = (float*)(smem + FL_STATS + 512);
    const int barid = WM + 1;

    for (int it = 0; it < 16; it++) {
        const uint32_t kvcur = sb + ((it & 1) ? FL_KV1 : FL_KV0);

        // ---- S = theta . phi^T ----
        float s[4][4];
        #pragma unroll
        for (int i = 0; i < 4; i++)
            #pragma unroll
            for (int r = 0; r < 4; r++) s[i][r] = 0.0f;
        #pragma unroll
        for (int slab = 0; slab < 4; slab++) {
            const uint32_t phS = kvcur + slab * 8192;
            #pragma unroll
            for (int ks = 0; ks < 4; ks++) {
                uint32_t bfr[2][4];
                ldsm4(bfr[0], phS + SWZ((uint32_t)((WN * 32 + arow) * 128 + ks * 32 + ksel)));
                ldsm4(bfr[1], phS + SWZ((uint32_t)((WN * 32 + 16 + arow) * 128 + ks * 32 + ksel)));
                #pragma unroll
                for (int nt = 0; nt < 4; nt++)
                    mma_bf16(s[nt], af_all[slab][ks],
                             bfr[nt >> 1][nt & 1], bfr[nt >> 1][(nt & 1) + 2]);
            }
        }

        // ---- online softmax ----
        float vlo = -1e30f, vhi = -1e30f;
        #pragma unroll
        for (int nt = 0; nt < 4; nt++) {
            vlo = fmaxf(vlo, fmaxf(s[nt][0], s[nt][1]));
            vhi = fmaxf(vhi, fmaxf(s[nt][2], s[nt][3]));
        }
        vlo = fmaxf(vlo, __shfl_xor_sync(0xffffffffu, vlo, 1));
        vlo = fmaxf(vlo, __shfl_xor_sync(0xffffffffu, vlo, 2));
        vhi = fmaxf(vhi, __shfl_xor_sync(0xffffffffu, vhi, 1));
        vhi = fmaxf(vhi, __shfl_xor_sync(0xffffffffu, vhi, 2));
        if (tg == 0) { pmax[WN * 64 + rlo] = vlo; pmax[WN * 64 + rhi] = vhi; }
        bar_pair(barid);
        const float mnlo = fmaxf(m_lo, fmaxf(pmax[rlo], pmax[64 + rlo]));
        const float mnhi = fmaxf(m_hi, fmaxf(pmax[rhi], pmax[64 + rhi]));
        const float clo = __expf(m_lo - mnlo), chi = __expf(m_hi - mnhi);
        m_lo = mnlo; m_hi = mnhi;

        float slo = 0.0f, shi = 0.0f;
        #pragma unroll
        for (int nt = 0; nt < 4; nt++) {
            s[nt][0] = __expf(s[nt][0] - mnlo); s[nt][1] = __expf(s[nt][1] - mnlo);
            s[nt][2] = __expf(s[nt][2] - mnhi); s[nt][3] = __expf(s[nt][3] - mnhi);
            slo += s[nt][0] + s[nt][1];
            shi += s[nt][2] + s[nt][3];
        }
        l_lo = l_lo * clo + slo;
        l_hi = l_hi * chi + shi;

        #pragma unroll
        for (int nt = 0; nt < 16; nt++) {
            acc_o[nt][0] *= clo; acc_o[nt][1] *= clo;
            acc_o[nt][2] *= chi; acc_o[nt][3] *= chi;
        }

        // P tile into staging
        #pragma unroll
        for (int nt = 0; nt < 4; nt++) {
            const int col = WN * 32 + nt * 8 + tg * 2;
            *(__nv_bfloat162*)(smem + SWZ((uint32_t)(rlo * 128 + col * 2))) =
                __floats2bfloat162_rn(s[nt][0], s[nt][1]);
            *(__nv_bfloat162*)(smem + SWZ((uint32_t)(rhi * 128 + col * 2))) =
                __floats2bfloat162_rn(s[nt][2], s[nt][3]);
        }
        bar_pair(barid);

        // ---- O += P . gv^T ----
        const uint32_t gvS = kvcur + 32768;
        #pragma unroll
        for (int ks = 0; ks < 4; ks++) {
            uint32_t pf[4];
            ldsm4(pf, sb + SWZ((uint32_t)((WM * 16 + arow) * 128 + ks * 32 + ksel)));
            #pragma unroll
            for (int h = 0; h < 8; h++) {
                uint32_t gf[4];
                ldsm4(gf, gvS + SWZ((uint32_t)((WN * 128 + h * 16 + arow) * 128 + ks * 32 + ksel)));
                mma_bf16(acc_o[2 * h],     pf, gf[0], gf[2]);
                mma_bf16(acc_o[2 * h + 1], pf, gf[1], gf[3]);
            }
        }
        __syncthreads();
        if (it + 2 < 16) {
            issue_kv(it + 2, kvcur);
            asm volatile("cp.async.commit_group;" ::: "memory");
            asm volatile("cp.async.wait_group 1;" ::: "memory");
            __syncthreads();
        } else if (it + 1 < 16) {
            asm volatile("cp.async.wait_group 0;" ::: "memory");
            __syncthreads();
        }
    }

    // stream ow through kv buffers (all kv reads complete)
    issue_ow(0, sb + FL_KV0);
    asm volatile("cp.async.commit_group;" ::: "memory");
    issue_ow(1, sb + FL_KV1);
    asm volatile("cp.async.commit_group;" ::: "memory");

    // final l reduction
    l_lo += __shfl_xor_sync(0xffffffffu, l_lo, 1);
    l_lo += __shfl_xor_sync(0xffffffffu, l_lo, 2);
    l_hi += __shfl_xor_sync(0xffffffffu, l_hi, 1);
    l_hi += __shfl_xor_sync(0xffffffffu, l_hi, 2);
    if (tg == 0) { psum[WN * 64 + rlo] = l_lo; psum[WN * 64 + rhi] = l_hi; }
    bar_pair(barid);
    const float ilo = 1.0f / (psum[rlo] + psum[64 + rlo]);
    const float ihi = 1.0f / (psum[rhi] + psum[64 + rhi]);

    // normalized O (bf16) into staging as 4 e-slabs of [64q x 128B]
    #pragma unroll
    for (int nt = 0; nt < 16; nt++) {
        const int e = WN * 128 + nt * 8 + tg * 2;
        const int slab = e >> 6, el = e & 63;
        *(__nv_bfloat162*)(smem + slab * 8192 + SWZ((uint32_t)(rlo * 128 + el * 2))) =
            __floats2bfloat162_rn(acc_o[nt][0] * ilo, acc_o[nt][1] * ilo);
        *(__nv_bfloat162*)(smem + slab * 8192 + SWZ((uint32_t)(rhi * 128 + el * 2))) =
            __floats2bfloat162_rn(acc_o[nt][2] * ihi, acc_o[nt][3] * ihi);
    }
    __syncthreads();

    // O fragments (A operand of the projection GEMM)
    uint32_t of[4][4][4];
    #pragma unroll
    for (int slab = 0; slab < 4; slab++)
        #pragma unroll
        for (int ks = 0; ks < 4; ks++)
            ldsm4(of[slab][ks],
                  sb + slab * 8192 + SWZ((uint32_t)((WM * 16 + arow) * 128 + ks * 32 + ksel)));

    // F[q][c] = O . ow^T, 4 c-slabs of 64, written f32 to out
    float* out2 = OutF + (long)z * (512L * 4096) + 256L * 4096 + q0;
    for (int cs = 0; cs < 4; cs++) {
        const uint32_t kvc = sb + ((cs & 1) ? FL_KV1 : FL_KV0);
        if (cs < 3) { asm volatile("cp.async.wait_group 1;" ::: "memory"); }
        else        { asm volatile("cp.async.wait_group 0;" ::: "memory"); }
        __syncthreads();

        float accf[4][4];
        #pragma unroll
        for (int i = 0; i < 4; i++)
            #pragma unroll
            for (int r = 0; r < 4; r++) accf[i][r] = 0.0f;

        #pragma unroll
        for (int slab = 0; slab < 4; slab++) {
            const uint32_t wS = kvc + slab * 8192;
            #pragma unroll
            for (int ks = 0; ks < 4; ks++) {
                uint32_t bfr[2][4];
                ldsm4(bfr[0], wS + SWZ((uint32_t)((WN * 32 + arow) * 128 + ks * 32 + ksel)));
                ldsm4(bfr[1], wS + SWZ((uint32_t)((WN * 32 + 16 + arow) * 128 + ks * 32 + ksel)));
                #pragma unroll
                for (int nt = 0; nt < 4; nt++)
                    mma_bf16(accf[nt], of[slab][ks],
                             bfr[nt >> 1][nt & 1], bfr[nt >> 1][(nt & 1) + 2]);
            }
        }

        #pragma unroll
        for (int nt = 0; nt < 4; nt++) {
            const int c = cs * 64 + WN * 32 + nt * 8 + tg * 2;
            out2[(long)c * 4096 + rlo]       = accf[nt][0];
            out2[(long)(c + 1) * 4096 + rlo] = accf[nt][1];
            out2[(long)c * 4096 + rhi]       = accf[nt][2];
            out2[(long)(c + 1) * 4096 + rhi] = accf[nt][3];
        }

        if (cs + 2 < 4) {
            __syncthreads();
            issue_ow(cs + 2, kvc);
            asm volatile("cp.async.commit_group;" ::: "memory");
        }
    }
}

// ============== transpose+convert (+ optional copy-through to out) ==============
__global__ __launch_bounds__(256) void transcvt_kernel(
    const float* __restrict__ in, bf16* __restrict__ out,
    float* __restrict__ copyDst, int Cc)
{
    __shared__ float t[32][33];
    const long base = (long)blockIdx.z * 256 * Cc;
    const int c0 = blockIdx.x * 32, r0 = blockIdx.y * 32;
    const int tx = threadIdx.x, ty = threadIdx.y;
    #pragma unroll
    for (int i = 0; i < 4; i++) {
        float v = in[base + (long)(r0 + ty + i * 8) * Cc + c0 + tx];
        t[ty + i * 8][tx] = v;
        if (copyDst)
            copyDst[(long)blockIdx.z * (512L * 4096) + (long)(r0 + ty + i * 8) * Cc + c0 + tx] = v;
    }
    __syncthreads();
    #pragma unroll
    for (int i = 0; i < 4; i++)
        out[base + (long)(c0 + ty + i * 8) * 256 + r0 + tx] = __float2bfloat16(t[tx][ty + i * 8]);
}

__global__ __launch_bounds__(256) void cvt4_kernel(
    const float* __restrict__ a, const float* __restrict__ b,
    const float* __restrict__ c, const float* __restrict__ d,
    bf16* __restrict__ out)
{
    const float* srcs[4] = {a, b, c, d};
    int j = (blockIdx.x * 256 + threadIdx.x) * 4;
    float4 v = *(const float4*)(srcs[j >> 16] + (j & 65535));
    *(__nv_bfloat162*)&out[j]     = __floats2bfloat162_rn(v.x, v.y);
    *(__nv_bfloat162*)&out[j + 2] = __floats2bfloat162_rn(v.z, v.w);
}

extern "C" void kernel_launch(void* const* d_in, const int* in_sizes, int n_in,
                              void* d_out, int out_size)
{
    const float* C   = (const float*)d_in[0];
    const float* P   = (const float*)d_in[1];
    const float* thw = (const float*)d_in[2];
    const float* phw = (const float*)d_in[3];
    const float* gw  = (const float*)d_in[4];
    const float* ow  = (const float*)d_in[5];
    float* out = (float*)d_out;

    bf16 *w16, *CTb, *PTb, *thetaT, *phiT, *gv;
    cudaGetSymbolAddress((void**)&w16, g_w16);
    cudaGetSymbolAddress((void**)&CTb, g_CTb);
    cudaGetSymbolAddress((void**)&PTb, g_PTb);
    cudaGetSymbolAddress((void**)&thetaT, g_thetaT);
    cudaGetSymbolAddress((void**)&phiT, g_phiT);
    cudaGetSymbolAddress((void**)&gv, g_gv);

    static cudaStream_t s1 = nullptr;
    static cudaEvent_t evStart = nullptr, evCvt = nullptr, evB = nullptr;
    if (s1 == nullptr) {
        cudaFuncSetAttribute(gemm_bf16_kernel,
                             cudaFuncAttributeMaxDynamicSharedMemorySize, 98304);
        cudaFuncSetAttribute(flash_kernel,
                             cudaFuncAttributeMaxDynamicSharedMemorySize, FL_TOTAL);
        cudaStreamCreateWithFlags(&s1, cudaStreamNonBlocking);
        cudaEventCreateWithFlags(&evStart, cudaEventDisableTiming);
        cudaEventCreateWithFlags(&evCvt, cudaEventDisableTiming);
        cudaEventCreateWithFlags(&evB, cudaEventDisableTiming);
    }

    const dim3 blk(256);
    const long NQ = 4096, NKV = 1024;

    // ---- fork side chain (B): transcvtP -> stage2+3 on s1 ----
    cudaEventRecord(evStart, 0);
    cudaStreamWaitEvent(s1, evStart, 0);
    transcvt_kernel<<<dim3(32, 8, 8), dim3(32, 8), 0, s1>>>(P, PTb, nullptr, 1024);

    // ---- main chain (A) on stream 0 ----
    cvt4_kernel<<<256, blk>>>(thw, phw, gw, ow, w16);
    cudaEventRecord(evCvt, 0);

    // chain B continues: stage2+3 needs w16 (evCvt) + PTb (s1-ordered)
    cudaStreamWaitEvent(s1, evCvt, 0);
    gemm_bf16_kernel<<<dim3(4, 8, 8), blk, 98304, s1>>>(w16 + 65536, PTb, phiT, gv, 256,
        256, 0, 256, NKV * 256, NKV * 256, 256, 256 * NKV, 1024, 1.0f);
    cudaEventRecord(evB, s1);

    // chain A continues: transcvtC (+copy to out half 1) -> stage1
    transcvt_kernel<<<dim3(128, 8, 8), dim3(32, 8)>>>(C, CTb, out, 4096);
    gemm_bf16_kernel<<<dim3(2, 32, 8), blk, 98304>>>(w16, CTb, thetaT, nullptr, 256,
        256, 0, 256, NQ * 256, NQ * 256, 256, 0, 0, 0.0625f);

    // join: flash needs both chains
    cudaStreamWaitEvent(0, evB, 0);
    flash_kernel<<<dim3(64, 8), blk, FL_TOTAL>>>(thetaT, phiT, gv, w16 + 3 * 65536, out);
}

// round 14
// speedup vs baseline: 1.0878x; 1.0441x over previous
#include <cuda_runtime.h>
#include <cuda_bf16.h>
#include <cstdint>

typedef __nv_bfloat16 bf16;

// ---------------------------------------------------------------------------
// CrossModalAttention, sm_100:
//   stream-parallel prologue:
//     s0: cvt4 -> transcvtC                      (C also copied into out half 1)
//     s1: transcvtP -> stage2+3(phiT,gv)         (event fork/join)
//   flash kernel does stages 1,4,5,6,7:
//     prologue computes theta = (thw @ C)/16 in-CTA (thw streamed via kv bufs),
//     kv mainloop with online softmax, out_w projection epilogue -> out (f32).
// ---------------------------------------------------------------------------

__device__ bf16  g_w16   [4][65536];                 // thw, phw, gw, ow in bf16
__device__ bf16  g_CTb   [(size_t)8 * 4096 * 256];   // [B][Nq][CQ]
__device__ bf16  g_PTb   [(size_t)8 * 1024 * 256];   // [B][Nkv][CKV]
__device__ bf16  g_phiT  [(size_t)8 * 1024 * 256];   // [B][Nkv][E]
__device__ bf16  g_gv    [(size_t)8 * 256 * 1024];   // [B][E][Nkv]

#define SWZ(x) ((x) ^ (((x) >> 3) & 0x70))

__device__ __forceinline__ uint32_t smem_u32(const void* p) {
    uint32_t a;
    asm("{ .reg .u64 t; cvta.to.shared.u64 t, %1; cvt.u32.u64 %0, t; }" : "=r"(a) : "l"(p));
    return a;
}
__device__ __forceinline__ void cp16(uint32_t dst, const void* src) {
    asm volatile("cp.async.cg.shared.global [%0], [%1], 16;" :: "r"(dst), "l"(src) : "memory");
}
__device__ __forceinline__ void ldsm4(uint32_t* r, uint32_t a) {
    asm volatile("ldmatrix.sync.aligned.m8n8.x4.shared.b16 {%0,%1,%2,%3}, [%4];"
        : "=r"(r[0]), "=r"(r[1]), "=r"(r[2]), "=r"(r[3]) : "r"(a));
}
__device__ __forceinline__ void mma_bf16(float* c, const uint32_t* a, uint32_t b0, uint32_t b1) {
    asm volatile(
        "mma.sync.aligned.m16n8k16.row.col.f32.bf16.bf16.f32 "
        "{%0,%1,%2,%3},{%4,%5,%6,%7},{%8,%9},{%0,%1,%2,%3};"
        : "+f"(c[0]), "+f"(c[1]), "+f"(c[2]), "+f"(c[3])
        : "r"(a[0]), "r"(a[1]), "r"(a[2]), "r"(a[3]), "r"(b0), "r"(b1));
}
__device__ __forceinline__ void bar_pair(int id) {
    asm volatile("bar.sync %0, 64;" :: "r"(id) : "memory");
}

// ================= generic bf16 GEMM (stages 2+3 merged) =================
__global__ __launch_bounds__(256) void gemm_bf16_kernel(
    const bf16* __restrict__ A, const bf16* __restrict__ B,
    bf16* __restrict__ Out, bf16* __restrict__ Out2,
    int K, int as, long aB, int bs, long bB,
    long oB, int ldO, long oB2, int ldO2, float alpha)
{
    extern __shared__ char smem[];
    const uint32_t sb = smem_u32(smem);
    const int tid = threadIdx.x, warp = tid >> 5, lane = tid & 31;
    const int m0 = blockIdx.x * 128, n0 = blockIdx.y * 128;
    const bf16* Ab = A + (long)blockIdx.z * aB + (long)m0 * as;
    const bf16* Bb = B + (long)blockIdx.z * bB + (long)n0 * bs;

    int crow[4], ckc[4]; uint32_t cdst[4];
    #pragma unroll
    for (int j = 0; j < 4; j++) {
        int idx = tid + j * 256;
        crow[j] = idx >> 3; ckc[j] = idx & 7;
        cdst[j] = SWZ((uint32_t)(crow[j] * 128 + ckc[j] * 16));
    }
    const int nk = K >> 6;

    #define ISSUE(IT) do {                                                    \
        int _kt = (IT) * 64;                                                  \
        uint32_t _sA = sb + ((IT) % 3) * 32768, _sB = _sA + 16384;            \
        _Pragma("unroll")                                                     \
        for (int j = 0; j < 4; j++) {                                         \
            cp16(_sA + cdst[j], Ab + (long)crow[j] * as + _kt + ckc[j] * 8);  \
            cp16(_sB + cdst[j], Bb + (long)crow[j] * bs + _kt + ckc[j] * 8);  \
        }                                                                     \
    } while (0)

    #pragma unroll
    for (int s = 0; s < 2; s++) {
        if (s < nk) ISSUE(s);
        asm volatile("cp.async.commit_group;" ::: "memory");
    }

    float acc[4][4][4];
    #pragma unroll
    for (int i = 0; i < 4; i++)
        #pragma unroll
        for (int j = 0; j < 4; j++)
            #pragma unroll
            for (int r = 0; r < 4; r++) acc[i][j][r] = 0.0f;

    const int wm = warp & 1, wn = warp >> 1;
    const int arow = lane & 15;
    const int ksel = (lane >> 4) * 16;

    for (int it = 0; it < nk; it++) {
        if (it + 2 < nk) ISSUE(it + 2);
        asm volatile("cp.async.commit_group;" ::: "memory");
        asm volatile("cp.async.wait_group 2;" ::: "memory");
        __syncthreads();

        const uint32_t sA = sb + (it % 3) * 32768, sB = sA + 16384;
        #pragma unroll
        for (int ks = 0; ks < 64; ks += 16) {
            uint32_t af[4][4], bfr[2][4];
            #pragma unroll
            for (int mt = 0; mt < 4; mt++)
                ldsm4(af[mt], sA + SWZ((uint32_t)((wm * 64 + mt * 16 + arow) * 128 + ks * 2 + ksel)));
            #pragma unroll
            for (int h = 0; h < 2; h++)
                ldsm4(bfr[h], sB + SWZ((uint32_t)((wn * 32 + h * 16 + arow) * 128 + ks * 2 + ksel)));
            #pragma unroll
            for (int mt = 0; mt < 4; mt++)
                #pragma unroll
                for (int nt = 0; nt < 4; nt++)
                    mma_bf16(acc[mt][nt], af[mt],
                             bfr[nt >> 1][nt & 1], bfr[nt >> 1][(nt & 1) + 2]);
        }
        __syncthreads();
    }

    const int gid = lane >> 2, tg = lane & 3;
    const bool second = (Out2 != nullptr) && (m0 >= 256);
    #pragma unroll
    for (int mt = 0; mt < 4; mt++) {
        const int row = m0 + wm * 64 + mt * 16 + gid;
        #pragma unroll
        for (int nt = 0; nt < 4; nt++) {
            const int col = n0 + wn * 32 + nt * 8 + tg * 2;
            float v0 = acc[mt][nt][0] * alpha, v1 = acc[mt][nt][1] * alpha;
            float v2 = acc[mt][nt][2] * alpha, v3 = acc[mt][nt][3] * alpha;
            if (second) {
                bf16* O = Out2 + (long)blockIdx.z * oB2;
                const int r2 = row - 256;
                *(__nv_bfloat162*)&O[(long)r2 * ldO2 + col]       = __floats2bfloat162_rn(v0, v1);
                *(__nv_bfloat162*)&O[(long)(r2 + 8) * ldO2 + col] = __floats2bfloat162_rn(v2, v3);
            } else {
                bf16* O = Out + (long)blockIdx.z * oB;
                O[(long)col * ldO + row]           = __float2bfloat16(v0);
                O[(long)(col + 1) * ldO + row]     = __float2bfloat16(v1);
                O[(long)col * ldO + row + 8]       = __float2bfloat16(v2);
                O[(long)(col + 1) * ldO + row + 8] = __float2bfloat16(v3);
            }
        }
    }
}

// ================= fused flash kernel (stages 1,4,5,6,7) =================
// smem: [0,32K) staging: CT tile -> theta tile -> P tile -> O tile;
//       kv0 32K..96K ; kv1 96K..160K (prologue: thw slabs; mainloop: phi+gv;
//       epilogue: ow slabs); stats at 160K.
#define FL_KV0   32768
#define FL_KV1   98304
#define FL_STATS 163840
#define FL_TOTAL 164864

__global__ __launch_bounds__(256) void flash_kernel(
    const bf16* __restrict__ CT, const bf16* __restrict__ Thw,
    const bf16* __restrict__ Ph, const bf16* __restrict__ Gv,
    const bf16* __restrict__ Ow, float* __restrict__ OutF)
{
    extern __shared__ char smem[];
    const uint32_t sb = smem_u32(smem);
    const int tid = threadIdx.x, warp = tid >> 5, lane = tid & 31;
    const int WM = warp >> 1, WN = warp & 1;
    const int gid = lane >> 2, tg = lane & 3;
    const int arow = lane & 15, ksel = (lane >> 4) * 16;
    const int q0 = blockIdx.x * 64, z = blockIdx.y;

    const bf16* CTB = CT + ((long)z * 4096 + q0) * 256;
    const bf16* PhB = Ph + (long)z * 1024 * 256;
    const bf16* GvB = Gv + (long)z * 256 * 1024;

    auto issue_kv = [&](int jj, uint32_t kvbase) {
        const bf16* ph = PhB + jj * 64 * 256;
        #pragma unroll
        for (int j = 0; j < 8; j++) {
            int i = tid + j * 256, row = i >> 5, c16 = i & 31;
            cp16(kvbase + (c16 >> 3) * 8192 + SWZ((uint32_t)(row * 128 + (c16 & 7) * 16)),
                 ph + row * 256 + c16 * 8);
        }
        const bf16* gvp = GvB + jj * 64;
        #pragma unroll
        for (int j = 0; j < 8; j++) {
            int i = tid + j * 256, e = i >> 3, cw = i & 7;
            cp16(kvbase + 32768 + SWZ((uint32_t)(e * 128 + cw * 16)),
                 gvp + e * 1024 + cw * 8);
        }
    };
    // stream a 64-row slab of a [256 x 256] k-major weight matrix (thw or ow)
    auto issue_w = [&](const bf16* W, int cs, uint32_t kvbase) {
        const bf16* wp = W + cs * 64 * 256;
        #pragma unroll
        for (int j = 0; j < 8; j++) {
            int i = tid + j * 256, row = i >> 5, c16 = i & 31;
            cp16(kvbase + (c16 >> 3) * 8192 + SWZ((uint32_t)(row * 128 + (c16 & 7) * 16)),
                 wp + row * 256 + c16 * 8);
        }
    };

    // ---- prologue A: CT tile + thw slab0 (group 0), thw slab1 (group 1) ----
    #pragma unroll
    for (int j = 0; j < 8; j++) {
        int i = tid + j * 256, row = i >> 5, c16 = i & 31;
        cp16(sb + (c16 >> 3) * 8192 + SWZ((uint32_t)(row * 128 + (c16 & 7) * 16)),
             CTB + row * 256 + c16 * 8);
    }
    issue_w(Thw, 0, sb + FL_KV0);
    asm volatile("cp.async.commit_group;" ::: "memory");
    issue_w(Thw, 1, sb + FL_KV1);
    asm volatile("cp.async.commit_group;" ::: "memory");

    asm volatile("cp.async.wait_group 1;" ::: "memory");
    __syncthreads();

    // CT fragments -> registers (reused later for theta fragments)
    uint32_t af_all[4][4][4];
    #pragma unroll
    for (int slab = 0; slab < 4; slab++)
        #pragma unroll
        for (int ks = 0; ks < 4; ks++)
            ldsm4(af_all[slab][ks],
                  sb + slab * 8192 + SWZ((uint32_t)((WM * 16 + arow) * 128 + ks * 32 + ksel)));
    __syncthreads();   // staging free for theta

    const int rlo = WM * 16 + gid, rhi = rlo + 8;

    // ---- prologue B: theta[64q][256e] = (thw @ CT^T)/16, 4 e-slabs of 64 ----
    for (int cs = 0; cs < 4; cs++) {
        const uint32_t kvc = sb + ((cs & 1) ? FL_KV1 : FL_KV0);
        if (cs > 0) {
            if (cs < 3) { asm volatile("cp.async.wait_group 1;" ::: "memory"); }
            else        { asm volatile("cp.async.wait_group 0;" ::: "memory"); }
            __syncthreads();
        }

        float accf[4][4];
        #pragma unroll
        for (int i = 0; i < 4; i++)
            #pragma unroll
            for (int r = 0; r < 4; r++) accf[i][r] = 0.0f;

        #pragma unroll
        for (int slab = 0; slab < 4; slab++) {
            const uint32_t wS = kvc + slab * 8192;
            #pragma unroll
            for (int ks = 0; ks < 4; ks++) {
                uint32_t bfr[2][4];
                ldsm4(bfr[0], wS + SWZ((uint32_t)((WN * 32 + arow) * 128 + ks * 32 + ksel)));
                ldsm4(bfr[1], wS + SWZ((uint32_t)((WN * 32 + 16 + arow) * 128 + ks * 32 + ksel)));
                #pragma unroll
                for (int nt = 0; nt < 4; nt++)
                    mma_bf16(accf[nt], af_all[slab][ks],
                             bfr[nt >> 1][nt & 1], bfr[nt >> 1][(nt & 1) + 2]);
            }
        }

        // theta slab (bf16, alpha=1/16) into staging slab cs: [64 q][64 e]
        #pragma unroll
        for (int nt = 0; nt < 4; nt++) {
            const int col = WN * 32 + nt * 8 + tg * 2;
            *(__nv_bfloat162*)(smem + cs * 8192 + SWZ((uint32_t)(rlo * 128 + col * 2))) =
                __floats2bfloat162_rn(accf[nt][0] * 0.0625f, accf[nt][1] * 0.0625f);
            *(__nv_bfloat162*)(smem + cs * 8192 + SWZ((uint32_t)(rhi * 128 + col * 2))) =
                __floats2bfloat162_rn(accf[nt][2] * 0.0625f, accf[nt][3] * 0.0625f);
        }

        if (cs + 2 < 4) {
            __syncthreads();                    // all reads of kvc done
            issue_w(Thw, cs + 2, kvc);
            asm volatile("cp.async.commit_group;" ::: "memory");
        }
    }
    __syncthreads();   // theta staging complete

    // theta fragments -> registers
    #pragma unroll
    for (int slab = 0; slab < 4; slab++)
        #pragma unroll
        for (int ks = 0; ks < 4; ks++)
            ldsm4(af_all[slab][ks],
                  sb + slab * 8192 + SWZ((uint32_t)((WM * 16 + arow) * 128 + ks * 32 + ksel)));

    // start kv pipeline (kv buffers are free; all thw reads done)
    issue_kv(0, sb + FL_KV0);
    asm volatile("cp.async.commit_group;" ::: "memory");
    issue_kv(1, sb + FL_KV1);
    asm volatile("cp.async.commit_group;" ::: "memory");
    asm volatile("cp.async.wait_group 1;" ::: "memory");
    __syncthreads();   // kv0 ready; staging now reusable as P

    float m_lo = -1e30f, m_hi = -1e30f, l_lo = 0.0f, l_hi = 0.0f;
    float acc_o[16][4];
    #pragma unroll
    for (int i = 0; i < 16; i++)
        #pragma unroll
        for (int r = 0; r < 4; r++) acc_o[i][r] = 0.0f;

    float* pmax = (float*)(smem + FL_STATS);
    float* psum = (float*)(smem + FL_STATS + 512);
    const int barid = WM + 1;

    for (int it = 0; it < 16; it++) {
        const uint32_t kvcur = sb + ((it & 1) ? FL_KV1 : FL_KV0);

        // ---- S = theta . phi^T ----
        float s[4][4];
        #pragma unroll
        for (int i = 0; i < 4; i++)
            #pragma unroll
            for (int r = 0; r < 4; r++) s[i][r] = 0.0f;
        #pragma unroll
        for (int slab = 0; slab < 4; slab++) {
            const uint32_t phS = kvcur + slab * 8192;
            #pragma unroll
            for (int ks = 0; ks < 4; ks++) {
                uint32_t bfr[2][4];
                ldsm4(bfr[0], phS + SWZ((uint32_t)((WN * 32 + arow) * 128 + ks * 32 + ksel)));
                ldsm4(bfr[1], phS + SWZ((uint32_t)((WN * 32 + 16 + arow) * 128 + ks * 32 + ksel)));
                #pragma unroll
                for (int nt = 0; nt < 4; nt++)
                    mma_bf16(s[nt], af_all[slab][ks],
                             bfr[nt >> 1][nt & 1], bfr[nt >> 1][(nt & 1) + 2]);
            }
        }

        // ---- online softmax ----
        float vlo = -1e30f, vhi = -1e30f;
        #pragma unroll
        for (int nt = 0; nt < 4; nt++) {
            vlo = fmaxf(vlo, fmaxf(s[nt][0], s[nt][1]));
            vhi = fmaxf(vhi, fmaxf(s[nt][2], s[nt][3]));
        }
        vlo = fmaxf(vlo, __shfl_xor_sync(0xffffffffu, vlo, 1));
        vlo = fmaxf(vlo, __shfl_xor_sync(0xffffffffu, vlo, 2));
        vhi = fmaxf(vhi, __shfl_xor_sync(0xffffffffu, vhi, 1));
        vhi = fmaxf(vhi, __shfl_xor_sync(0xffffffffu, vhi, 2));
        if (tg == 0) { pmax[WN * 64 + rlo] = vlo; pmax[WN * 64 + rhi] = vhi; }
        bar_pair(barid);
        const float mnlo = fmaxf(m_lo, fmaxf(pmax[rlo], pmax[64 + rlo]));
        const float mnhi = fmaxf(m_hi, fmaxf(pmax[rhi], pmax[64 + rhi]));
        const float clo = __expf(m_lo - mnlo), chi = __expf(m_hi - mnhi);
        m_lo = mnlo; m_hi = mnhi;

        float slo = 0.0f, shi = 0.0f;
        #pragma unroll
        for (int nt = 0; nt < 4; nt++) {
            s[nt][0] = __expf(s[nt][0] - mnlo); s[nt][1] = __expf(s[nt][1] - mnlo);
            s[nt][2] = __expf(s[nt][2] - mnhi); s[nt][3] = __expf(s[nt][3] - mnhi);
            slo += s[nt][0] + s[nt][1];
            shi += s[nt][2] + s[nt][3];
        }
        l_lo = l_lo * clo + slo;
        l_hi = l_hi * chi + shi;

        #pragma unroll
        for (int nt = 0; nt < 16; nt++) {
            acc_o[nt][0] *= clo; acc_o[nt][1] *= clo;
            acc_o[nt][2] *= chi; acc_o[nt][3] *= chi;
        }

        // P tile into staging
        #pragma unroll
        for (int nt = 0; nt < 4; nt++) {
            const int col = WN * 32 + nt * 8 + tg * 2;
            *(__nv_bfloat162*)(smem + SWZ((uint32_t)(rlo * 128 + col * 2))) =
                __floats2bfloat162_rn(s[nt][0], s[nt][1]);
            *(__nv_bfloat162*)(smem + SWZ((uint32_t)(rhi * 128 + col * 2))) =
                __floats2bfloat162_rn(s[nt][2], s[nt][3]);
        }
        bar_pair(barid);

        // ---- O += P . gv^T ----
        const uint32_t gvS = kvcur + 32768;
        #pragma unroll
        for (int ks = 0; ks < 4; ks++) {
            uint32_t pf[4];
            ldsm4(pf, sb + SWZ((uint32_t)((WM * 16 + arow) * 128 + ks * 32 + ksel)));
            #pragma unroll
            for (int h = 0; h < 8; h++) {
                uint32_t gf[4];
                ldsm4(gf, gvS + SWZ((uint32_t)((WN * 128 + h * 16 + arow) * 128 + ks * 32 + ksel)));
                mma_bf16(acc_o[2 * h],     pf, gf[0], gf[2]);
                mma_bf16(acc_o[2 * h + 1], pf, gf[1], gf[3]);
            }
        }
        __syncthreads();
        if (it + 2 < 16) {
            issue_kv(it + 2, kvcur);
            asm volatile("cp.async.commit_group;" ::: "memory");
            asm volatile("cp.async.wait_group 1;" ::: "memory");
            __syncthreads();
        } else if (it + 1 < 16) {
            asm volatile("cp.async.wait_group 0;" ::: "memory");
            __syncthreads();
        }
    }

    // stream ow through kv buffers (all kv reads complete)
    issue_w(Ow, 0, sb + FL_KV0);
    asm volatile("cp.async.commit_group;" ::: "memory");
    issue_w(Ow, 1, sb + FL_KV1);
    asm volatile("cp.async.commit_group;" ::: "memory");

    // final l reduction
    l_lo += __shfl_xor_sync(0xffffffffu, l_lo, 1);
    l_lo += __shfl_xor_sync(0xffffffffu, l_lo, 2);
    l_hi += __shfl_xor_sync(0xffffffffu, l_hi, 1);
    l_hi += __shfl_xor_sync(0xffffffffu, l_hi, 2);
    if (tg == 0) { psum[WN * 64 + rlo] = l_lo; psum[WN * 64 + rhi] = l_hi; }
    bar_pair(barid);
    const float ilo = 1.0f / (psum[rlo] + psum[64 + rlo]);
    const float ihi = 1.0f / (psum[rhi] + psum[64 + rhi]);

    // normalized O (bf16) into staging as 4 e-slabs of [64q x 128B]
    #pragma unroll
    for (int nt = 0; nt < 16; nt++) {
        const int e = WN * 128 + nt * 8 + tg * 2;
        const int slab = e >> 6, el = e & 63;
        *(__nv_bfloat162*)(smem + slab * 8192 + SWZ((uint32_t)(rlo * 128 + el * 2))) =
            __floats2bfloat162_rn(acc_o[nt][0] * ilo, acc_o[nt][1] * ilo);
        *(__nv_bfloat162*)(smem + slab * 8192 + SWZ((uint32_t)(rhi * 128 + el * 2))) =
            __floats2bfloat162_rn(acc_o[nt][2] * ihi, acc_o[nt][3] * ihi);
    }
    __syncthreads();

    // O fragments (A operand of the projection GEMM)
    uint32_t of[4][4][4];
    #pragma unroll
    for (int slab = 0; slab < 4; slab++)
        #pragma unroll
        for (int ks = 0; ks < 4; ks++)
            ldsm4(of[slab][ks],
                  sb + slab * 8192 + SWZ((uint32_t)((WM * 16 + arow) * 128 + ks * 32 + ksel)));

    // F[q][c] = O . ow^T, 4 c-slabs of 64, written f32 to out
    float* out2 = OutF + (long)z * (512L * 4096) + 256L * 4096 + q0;
    for (int cs = 0; cs < 4; cs++) {
        const uint32_t kvc = sb + ((cs & 1) ? FL_KV1 : FL_KV0);
        if (cs < 3) { asm volatile("cp.async.wait_group 1;" ::: "memory"); }
        else        { asm volatile("cp.async.wait_group 0;" ::: "memory"); }
        __syncthreads();

        float accf[4][4];
        #pragma unroll
        for (int i = 0; i < 4; i++)
            #pragma unroll
            for (int r = 0; r < 4; r++) accf[i][r] = 0.0f;

        #pragma unroll
        for (int slab = 0; slab < 4; slab++) {
            const uint32_t wS = kvc + slab * 8192;
            #pragma unroll
            for (int ks = 0; ks < 4; ks++) {
                uint32_t bfr[2][4];
                ldsm4(bfr[0], wS + SWZ((uint32_t)((WN * 32 + arow) * 128 + ks * 32 + ksel)));
                ldsm4(bfr[1], wS + SWZ((uint32_t)((WN * 32 + 16 + arow) * 128 + ks * 32 + ksel)));
                #pragma unroll
                for (int nt = 0; nt < 4; nt++)
                    mma_bf16(accf[nt], of[slab][ks],
                             bfr[nt >> 1][nt & 1], bfr[nt >> 1][(nt & 1) + 2]);
            }
        }

        #pragma unroll
        for (int nt = 0; nt < 4; nt++) {
            const int c = cs * 64 + WN * 32 + nt * 8 + tg * 2;
            out2[(long)c * 4096 + rlo]       = accf[nt][0];
            out2[(long)(c + 1) * 4096 + rlo] = accf[nt][1];
            out2[(long)c * 4096 + rhi]       = accf[nt][2];
            out2[(long)(c + 1) * 4096 + rhi] = accf[nt][3];
        }

        if (cs + 2 < 4) {
            __syncthreads();
            issue_w(Ow, cs + 2, kvc);
            asm volatile("cp.async.commit_group;" ::: "memory");
        }
    }
}

// ============== transpose+convert (+ optional copy-through to out) ==============
__global__ __launch_bounds__(256) void transcvt_kernel(
    const float* __restrict__ in, bf16* __restrict__ out,
    float* __restrict__ copyDst, int Cc)
{
    __shared__ float t[32][33];
    const long base = (long)blockIdx.z * 256 * Cc;
    const int c0 = blockIdx.x * 32, r0 = blockIdx.y * 32;
    const int tx = threadIdx.x, ty = threadIdx.y;
    #pragma unroll
    for (int i = 0; i < 4; i++) {
        float v = in[base + (long)(r0 + ty + i * 8) * Cc + c0 + tx];
        t[ty + i * 8][tx] = v;
        if (copyDst)
            copyDst[(long)blockIdx.z * (512L * 4096) + (long)(r0 + ty + i * 8) * Cc + c0 + tx] = v;
    }
    __syncthreads();
    #pragma unroll
    for (int i = 0; i < 4; i++)
        out[base + (long)(c0 + ty + i * 8) * 256 + r0 + tx] = __float2bfloat16(t[tx][ty + i * 8]);
}

__global__ __launch_bounds__(256) void cvt4_kernel(
    const float* __restrict__ a, const float* __restrict__ b,
    const float* __restrict__ c, const float* __restrict__ d,
    bf16* __restrict__ out)
{
    const float* srcs[4] = {a, b, c, d};
    int j = (blockIdx.x * 256 + threadIdx.x) * 4;
    float4 v = *(const float4*)(srcs[j >> 16] + (j & 65535));
    *(__nv_bfloat162*)&out[j]     = __floats2bfloat162_rn(v.x, v.y);
    *(__nv_bfloat162*)&out[j + 2] = __floats2bfloat162_rn(v.z, v.w);
}

extern "C" void kernel_launch(void* const* d_in, const int* in_sizes, int n_in,
                              void* d_out, int out_size)
{
    const float* C   = (const float*)d_in[0];
    const float* P   = (const float*)d_in[1];
    const float* thw = (const float*)d_in[2];
    const float* phw = (const float*)d_in[3];
    const float* gw  = (const float*)d_in[4];
    const float* ow  = (const float*)d_in[5];
    float* out = (float*)d_out;

    bf16 *w16, *CTb, *PTb, *phiT, *gv;
    cudaGetSymbolAddress((void**)&w16, g_w16);
    cudaGetSymbolAddress((void**)&CTb, g_CTb);
    cudaGetSymbolAddress((void**)&PTb, g_PTb);
    cudaGetSymbolAddress((void**)&phiT, g_phiT);
    cudaGetSymbolAddress((void**)&gv, g_gv);

    static cudaStream_t s1 = nullptr;
    static cudaEvent_t evStart = nullptr, evCvt = nullptr, evB = nullptr;
    if (s1 == nullptr) {
        cudaFuncSetAttribute(gemm_bf16_kernel,
                             cudaFuncAttributeMaxDynamicSharedMemorySize, 98304);
        cudaFuncSetAttribute(flash_kernel,
                             cudaFuncAttributeMaxDynamicSharedMemorySize, FL_TOTAL);
        cudaStreamCreateWithFlags(&s1, cudaStreamNonBlocking);
        cudaEventCreateWithFlags(&evStart, cudaEventDisableTiming);
        cudaEventCreateWithFlags(&evCvt, cudaEventDisableTiming);
        cudaEventCreateWithFlags(&evB, cudaEventDisableTiming);
    }

    const dim3 blk(256);
    const long NKV = 1024;

    // ---- fork side chain (B): transcvtP -> stage2+3 on s1 ----
    cudaEventRecord(evStart, 0);
    cudaStreamWaitEvent(s1, evStart, 0);
    transcvt_kernel<<<dim3(32, 8, 8), dim3(32, 8), 0, s1>>>(P, PTb, nullptr, 1024);

    // ---- main chain (A) on stream 0 ----
    cvt4_kernel<<<256, blk>>>(thw, phw, gw, ow, w16);
    cudaEventRecord(evCvt, 0);

    // chain B continues: stage2+3 needs w16 (evCvt) + PTb (s1-ordered)
    cudaStreamWaitEvent(s1, evCvt, 0);
    gemm_bf16_kernel<<<dim3(4, 8, 8), blk, 98304, s1>>>(w16 + 65536, PTb, phiT, gv, 256,
        256, 0, 256, NKV * 256, NKV * 256, 256, 256 * NKV, 1024, 1.0f);
    cudaEventRecord(evB, s1);

    // chain A continues: transcvtC (+copy to out half 1)
    transcvt_kernel<<<dim3(128, 8, 8), dim3(32, 8)>>>(C, CTb, out, 4096);

    // join: flash needs both chains; computes theta in-CTA from CTb + thw
    cudaStreamWaitEvent(0, evB, 0);
    flash_kernel<<<dim3(64, 8), blk, FL_TOTAL>>>(CTb, w16, phiT, gv,
                                                 w16 + 3 * 65536, out);
}